// round 12
// baseline (speedup 1.0000x reference)
#include <cuda_runtime.h>
#include <math.h>
#include <stdint.h>

#define NROWS 8192      // B*T
#define HD    640
#define NP    230
#define NM    96
#define TM    64        // rows per CTA
#define KC    32        // k per chunk
#define NCHUNK (HD / KC)  // 20
#define ASTRIDE 644     // floats per A row in smem; 644 % 32 == 4 -> conflict-free frags
#define P_PAD 258
#define M_PAD 97
#define MAXINV 32
#define NTHREADS 512

// ---- smem byte offsets ----
// A tile: 64 rows x ASTRIDE floats = 164864 bytes, loaded ONCE.
// epilogue aliases the A region:
#define SM_PHONE 0                        // 64*258*4 = 66048
#define SM_PH    66048                    // 64*97*4  = 24832 -> 90880 (< 164864)
// persistent tables (beyond A region):
#define SM_TBL   164864                   // icnt 96*4 -> 165248
#define SM_ILIST 165248                   // 96*32    -> 168320
#define SM_MAXV  168320                   // 64*4
#define SM_LSEV  168576                   // 64*4
#define SM_TOTAL 168832

__device__ float         g_Bp[NCHUNK * 8192];   // fragment-permuted B (tf32-rounded)
__device__ int           g_icnt[NM];
__device__ unsigned char g_ilist[NM * MAXINV];

// ---------------- helpers ----------------
__device__ __forceinline__ uint32_t smem_u32(const void* p) {
    uint32_t a;
    asm("{ .reg .u64 t; cvta.to.shared.u64 t, %1; cvt.u32.u64 %0, t; }" : "=r"(a) : "l"(p));
    return a;
}
__device__ __forceinline__ void cp16(uint32_t dst, const void* src) {
    asm volatile("cp.async.cg.shared.global [%0], [%1], 16;" :: "r"(dst), "l"(src));
}
#define CP_COMMIT() asm volatile("cp.async.commit_group;" ::: "memory")
#define CP_WAIT(N)  asm volatile("cp.async.wait_group %0;" :: "n"(N) : "memory")

// m16n8k8 tf32 MMA, D += A*B
__device__ __forceinline__ void mma_tf32(float* d, const uint32_t* a, uint32_t b0, uint32_t b1) {
    asm volatile(
        "mma.sync.aligned.m16n8k8.row.col.f32.tf32.tf32.f32 "
        "{%0,%1,%2,%3}, {%4,%5,%6,%7}, {%8,%9}, {%0,%1,%2,%3};"
        : "+f"(d[0]), "+f"(d[1]), "+f"(d[2]), "+f"(d[3])
        : "r"(a[0]), "r"(a[1]), "r"(a[2]), "r"(a[3]), "r"(b0), "r"(b1));
}

// ---------------- prologue kernel ----------------
// blocks 0..19: pack one 32-row chunk of B into fragment order via coalesced smem staging.
// blocks 20..31: inverse map, ONE phoneme per warp, rounds prefetched (MLP=8).
__global__ void prep_kernel(const float* __restrict__ f2p,
                            const float* __restrict__ mapping) {
    __shared__ float s[32 * 232];
    const int tid = threadIdx.x;
    const int b   = blockIdx.x;
    if (b < NCHUNK) {
        const float* src = f2p + (size_t)b * KC * NP;
        for (int idx = tid; idx < KC * NP; idx += 256) {
            int rr = idx / NP, c = idx - rr * NP;
            s[rr * 232 + c] = src[idx];
        }
        __syncthreads();
        float* dst = g_Bp + (size_t)b * 8192;
        for (int rem = tid; rem < 8192; rem += 256) {
            int nt   = rem >> 8;
            int r2   = rem & 255;
            int ks   = r2 >> 6;
            int lane = (r2 >> 1) & 31;
            int i    = r2 & 1;
            int n  = nt * 8 + (lane >> 2);
            int kk = ks * 8 + (lane & 3) + 4 * i;
            float v = (n < NP) ? s[kk * 232 + n] : 0.0f;
            uint32_t t;
            asm("cvt.rna.tf32.f32 %0, %1;" : "=r"(t) : "f"(v));
            dst[rem] = __uint_as_float(t);
        }
    } else {
        int wid  = tid >> 5;
        int lane = tid & 31;
        int m = (b - NCHUNK) * 8 + wid;   // 0..95, one phoneme per warp
        bool hit[8];
        #pragma unroll
        for (int rr = 0; rr < 8; rr++) {
            int p = rr * 32 + lane;
            hit[rr] = (p < NP) && (mapping[m * NP + p] > 0.0f);  // independent loads
        }
        int cnt = 0;
        #pragma unroll
        for (int rr = 0; rr < 8; rr++) {
            unsigned bal = __ballot_sync(0xffffffffu, hit[rr]);
            if (hit[rr]) {
                int pos = cnt + __popc(bal & ((1u << lane) - 1u));
                if (pos < MAXINV) g_ilist[m * MAXINV + pos] = (unsigned char)(rr * 32 + lane);
            }
            cnt += __popc(bal);
        }
        if (lane == 0) g_icnt[m] = (cnt < MAXINV) ? cnt : MAXINV;
    }
}

// ---------------- main kernel ----------------
// 512 threads = 16 warps (2 x 8); warp tile 32 x 32.
// A resident in smem; B prefetched into registers one chunk ahead (L2-resident g_Bp).
// NO barriers and NO async-waits in the mainloop.
__global__ __launch_bounds__(NTHREADS, 1)
void phon_mma_kernel(const float* __restrict__ enc, float* __restrict__ out) {
    extern __shared__ char smem[];
    const uint32_t sbase = smem_u32(smem);
    const int tid  = threadIdx.x;
    const int wid  = tid >> 5;
    const int lane = tid & 31;
    const int wm   = wid >> 3;   // 0..1  (32-row slice)
    const int wn   = wid & 7;    // 0..7  (32-col slice)
    const int row0 = blockIdx.x * TM;

    int*           sicnt  = (int*)(smem + SM_TBL);
    unsigned char* silist = (unsigned char*)(smem + SM_ILIST);
    float*         sMaxv  = (float*)(smem + SM_MAXV);
    float*         sLsev  = (float*)(smem + SM_LSEV);

    // stage inverse-map tables
    if (tid < NM) sicnt[tid] = g_icnt[tid];
    for (int i = tid; i < NM * MAXINV; i += NTHREADS) silist[i] = g_ilist[i];

    // stage the ENTIRE A tile: 64 rows x 640 floats = 10240 float4, 20 per thread
    #pragma unroll
    for (int it = 0; it < 20; it++) {
        int idx = tid + it * NTHREADS;
        int r = idx / 160;           // 160 float4 per row
        int g = idx - r * 160;
        cp16(sbase + (uint32_t)(r * ASTRIDE + g * 4) * 4,
             enc + (size_t)(row0 + r) * HD + g * 4);
    }
    CP_COMMIT();
    CP_WAIT(0);
    __syncthreads();   // A tile + tables visible to all warps

    const float* sA = (const float*)smem;

    float acc[2][4][4];
    #pragma unroll
    for (int i = 0; i < 2; i++)
        #pragma unroll
        for (int j = 0; j < 4; j++)
            #pragma unroll
            for (int c = 0; c < 4; c++) acc[i][j][c] = 0.0f;

    float2 bfrA[4][4], bfrB[4][4];   // [ks][j], two chunk-level buffers

    auto load_b = [&](int kc, float2 (*bfr)[4]) {
        const float* bch = g_Bp + (size_t)kc * 8192;
        #pragma unroll
        for (int j = 0; j < 4; j++)
            #pragma unroll
            for (int ks = 0; ks < 4; ks++)
                bfr[ks][j] = __ldg((const float2*)(bch + ((wn * 4 + j) * 4 + ks) * 64 + lane * 2));
    };

    auto mma_chunk = [&](const float2 (*bfr)[4], int kbase) {
        uint32_t afr[2][2][4];   // [slot][i][reg]
        auto load_afr = [&](int ks, int slot) {
            #pragma unroll
            for (int i = 0; i < 2; i++) {
                const float* ap = sA + (wm * 32 + i * 16 + (lane >> 2)) * ASTRIDE
                                     + kbase + ks * 8 + (lane & 3);
                afr[slot][i][0] = __float_as_uint(ap[0]);
                afr[slot][i][1] = __float_as_uint(ap[8 * ASTRIDE]);
                afr[slot][i][2] = __float_as_uint(ap[4]);
                afr[slot][i][3] = __float_as_uint(ap[8 * ASTRIDE + 4]);
            }
        };
        load_afr(0, 0);
        #pragma unroll
        for (int ks = 0; ks < 4; ks++) {
            const int cur = ks & 1;
            if (ks < 3) load_afr(ks + 1, cur ^ 1);   // prefetch next ks's A frags
            #pragma unroll
            for (int i = 0; i < 2; i++)
                #pragma unroll
                for (int j = 0; j < 4; j++)
                    mma_tf32(acc[i][j], afr[cur][i],
                             __float_as_uint(bfr[ks][j].x),
                             __float_as_uint(bfr[ks][j].y));
        }
    };

    // barrier-free mainloop, unrolled x2 to ping-pong B register buffers
    load_b(0, bfrA);
    #pragma unroll 1
    for (int kc = 0; kc < NCHUNK; kc += 2) {
        if (kc + 1 < NCHUNK) load_b(kc + 1, bfrB);   // prefetch next chunk's B
        mma_chunk(bfrA, kc * KC);
        if (kc + 2 < NCHUNK) load_b(kc + 2, bfrA);
        mma_chunk(bfrB, (kc + 1) * KC);
    }
    __syncthreads();   // all warps done reading sA before epilogue aliases it

    // ---- epilogue ----
    const float scale = 0.039528470752104741f;  // 1/sqrt(640)
    float* sPhone = (float*)(smem + SM_PHONE);
    float* sPh    = (float*)(smem + SM_PH);

    #pragma unroll
    for (int i = 0; i < 2; i++) {
        int r = wm * 32 + i * 16 + (lane >> 2);
        #pragma unroll
        for (int j = 0; j < 4; j++) {
            int c = wn * 32 + j * 8 + (lane & 3) * 2;
            float2 v0 = make_float2(acc[i][j][0] * scale, acc[i][j][1] * scale);
            float2 v1 = make_float2(acc[i][j][2] * scale, acc[i][j][3] * scale);
            *(float2*)(sPhone + r * P_PAD + c)       = v0;
            *(float2*)(sPhone + (r + 8) * P_PAD + c) = v1;
        }
    }
    __syncthreads();

    // gather-max via inverse map: 64 rows x 96 phonemes
    for (int idx = tid; idx < TM * NM; idx += NTHREADS) {
        int r = idx / NM;
        int m = idx - r * NM;
        int cnt = sicnt[m];
        const unsigned char* lst = silist + m * MAXINV;
        float mx = -INFINITY;
        for (int c = 0; c < cnt; c++)
            mx = fmaxf(mx, sPhone[r * P_PAD + lst[c]]);
        sPh[r * M_PAD + m] = mx;
    }
    __syncthreads();

    // per-row max + logsumexp: 4 threads per row (first 256 threads)
    if (tid < 256) {
        int r = tid >> 2;
        int q = tid & 3;
        const float* row = sPh + r * M_PAD;
        float mx = -INFINITY;
        #pragma unroll
        for (int m = q * 24; m < q * 24 + 24; m++) mx = fmaxf(mx, row[m]);
        mx = fmaxf(mx, __shfl_xor_sync(0xffffffffu, mx, 1));
        mx = fmaxf(mx, __shfl_xor_sync(0xffffffffu, mx, 2));
        float s = 0.0f;
        #pragma unroll
        for (int m = q * 24; m < q * 24 + 24; m++) s += expf(row[m] - mx);
        s += __shfl_xor_sync(0xffffffffu, s, 1);
        s += __shfl_xor_sync(0xffffffffu, s, 2);
        if (q == 0) { sMaxv[r] = mx; sLsev[r] = logf(s); }
    }
    __syncthreads();

    // coalesced output
    for (int idx = tid; idx < TM * NM; idx += NTHREADS) {
        int r = idx / NM;
        int m = idx - r * NM;
        out[(size_t)(row0 + r) * NM + m] = sPh[r * M_PAD + m] - sMaxv[r] - sLsev[r];
    }
}

extern "C" void kernel_launch(void* const* d_in, const int* in_sizes, int n_in,
                              void* d_out, int out_size) {
    const float* enc     = (const float*)d_in[0];
    const float* f2p     = (const float*)d_in[1];
    const float* mapping = (const float*)d_in[2];
    float*       out     = (float*)d_out;

    cudaFuncSetAttribute(phon_mma_kernel,
                         cudaFuncAttributeMaxDynamicSharedMemorySize, SM_TOTAL);

    prep_kernel<<<NCHUNK + 12, 256>>>(f2p, mapping);
    phon_mma_kernel<<<NROWS / TM, NTHREADS, SM_TOTAL>>>(enc, out);
}

// round 14
// speedup vs baseline: 1.1882x; 1.1882x over previous
#include <cuda_runtime.h>
#include <cuda_fp16.h>
#include <math.h>
#include <stdint.h>

#define NROWS 8192      // B*T
#define HD    640
#define NP    230
#define NM    96
#define TM    64        // rows per CTA
#define KC    32        // k per chunk
#define NCHUNK (HD / KC)  // 20
#define ASTRIDE 648     // floats per A row in smem; 648 % 32 == 8 -> conflict-free float2 LDS
#define P_PAD 258
#define M_PAD 97
#define MAXINV 32
#define NTHREADS 512

// ---- smem byte offsets ----
// A tile: 64 rows x ASTRIDE floats = 165888 bytes, loaded ONCE (fp32).
// epilogue aliases the A region:
#define SM_PHONE 0                        // 64*258*4 = 66048
#define SM_PH    66048                    // 64*97*4  = 24832 -> 90880 (< 165888)
// persistent tables (beyond A region):
#define SM_TBL   165888                   // icnt 96*4 -> 166272
#define SM_ILIST 166272                   // 96*32    -> 169344
#define SM_MAXV  169344                   // 64*4
#define SM_LSEV  169600                   // 64*4
#define SM_TOTAL 169856

// B packed as fp16x2 in m16n8k16 fragment order:
// [chunk][nt 32][ks16 2][lane 32][reg 2] uint32; 4096 uint32 per chunk.
__device__ uint32_t      g_Bp[NCHUNK * 4096];
__device__ int           g_icnt[NM];
__device__ unsigned char g_ilist[NM * MAXINV];

// ---------------- helpers ----------------
__device__ __forceinline__ uint32_t smem_u32(const void* p) {
    uint32_t a;
    asm("{ .reg .u64 t; cvta.to.shared.u64 t, %1; cvt.u32.u64 %0, t; }" : "=r"(a) : "l"(p));
    return a;
}
__device__ __forceinline__ void cp16(uint32_t dst, const void* src) {
    asm volatile("cp.async.cg.shared.global [%0], [%1], 16;" :: "r"(dst), "l"(src));
}
#define CP_COMMIT() asm volatile("cp.async.commit_group;" ::: "memory")
#define CP_WAIT(N)  asm volatile("cp.async.wait_group %0;" :: "n"(N) : "memory")

// m16n8k16 fp16 MMA, fp32 accum: D += A*B
__device__ __forceinline__ void mma_f16(float* d, const uint32_t* a, uint32_t b0, uint32_t b1) {
    asm volatile(
        "mma.sync.aligned.m16n8k16.row.col.f32.f16.f16.f32 "
        "{%0,%1,%2,%3}, {%4,%5,%6,%7}, {%8,%9}, {%0,%1,%2,%3};"
        : "+f"(d[0]), "+f"(d[1]), "+f"(d[2]), "+f"(d[3])
        : "r"(a[0]), "r"(a[1]), "r"(a[2]), "r"(a[3]), "r"(b0), "r"(b1));
}
// pack two fp32 into fp16x2 (lo -> .x/low half, hi -> high half)
__device__ __forceinline__ uint32_t packh2(float lo, float hi) {
    uint32_t r;
    asm("cvt.rn.f16x2.f32 %0, %1, %2;" : "=r"(r) : "f"(hi), "f"(lo));
    return r;
}

// ---------------- prologue kernel ----------------
// blocks 0..19: pack one 32-row chunk of B into fp16 m16n8k16 fragment order.
// blocks 20..31: inverse map, ONE phoneme per warp, rounds prefetched.
__global__ void prep_kernel(const float* __restrict__ f2p,
                            const float* __restrict__ mapping) {
    __shared__ float s[32 * 232];
    const int tid = threadIdx.x;
    const int b   = blockIdx.x;
    if (b < NCHUNK) {
        const float* src = f2p + (size_t)b * KC * NP;
        for (int idx = tid; idx < KC * NP; idx += 256) {
            int rr = idx / NP, c = idx - rr * NP;
            s[rr * 232 + c] = src[idx];
        }
        __syncthreads();
        uint32_t* dst = g_Bp + (size_t)b * 4096;
        for (int idx = tid; idx < 4096; idx += 256) {
            // idx = ((nt*2 + ks)*32 + lane)*2 + r2
            int r2   = idx & 1;
            int lane = (idx >> 1) & 31;
            int ks   = (idx >> 6) & 1;
            int nt   = idx >> 7;
            int n = nt * 8 + (lane >> 2);
            int k = ks * 16 + (lane & 3) * 2 + r2 * 8;     // within chunk
            float lo = (n < NP) ? s[k * 232 + n]       : 0.0f;
            float hi = (n < NP) ? s[(k + 1) * 232 + n] : 0.0f;
            dst[idx] = packh2(lo, hi);
        }
    } else {
        int wid  = tid >> 5;
        int lane = tid & 31;
        int m = (b - NCHUNK) * 8 + wid;   // 0..95
        bool hit[8];
        #pragma unroll
        for (int rr = 0; rr < 8; rr++) {
            int p = rr * 32 + lane;
            hit[rr] = (p < NP) && (mapping[m * NP + p] > 0.0f);
        }
        int cnt = 0;
        #pragma unroll
        for (int rr = 0; rr < 8; rr++) {
            unsigned bal = __ballot_sync(0xffffffffu, hit[rr]);
            if (hit[rr]) {
                int pos = cnt + __popc(bal & ((1u << lane) - 1u));
                if (pos < MAXINV) g_ilist[m * MAXINV + pos] = (unsigned char)(rr * 32 + lane);
            }
            cnt += __popc(bal);
        }
        if (lane == 0) g_icnt[m] = (cnt < MAXINV) ? cnt : MAXINV;
    }
}

// ---------------- main kernel ----------------
// 512 threads = 16 warps (2 x 8); warp tile 32 x 32, fp16 m16n8k16.
// A fp32 resident in smem; B fragments prefetched one chunk ahead from L2.
__global__ __launch_bounds__(NTHREADS, 1)
void phon_mma_kernel(const float* __restrict__ enc, float* __restrict__ out) {
    extern __shared__ char smem[];
    const uint32_t sbase = smem_u32(smem);
    const int tid  = threadIdx.x;
    const int wid  = tid >> 5;
    const int lane = tid & 31;
    const int wm   = wid >> 3;   // 0..1  (32-row slice)
    const int wn   = wid & 7;    // 0..7  (32-col slice)
    const int row0 = blockIdx.x * TM;

    int*           sicnt  = (int*)(smem + SM_TBL);
    unsigned char* silist = (unsigned char*)(smem + SM_ILIST);
    float*         sMaxv  = (float*)(smem + SM_MAXV);
    float*         sLsev  = (float*)(smem + SM_LSEV);

    if (tid < NM) sicnt[tid] = g_icnt[tid];
    for (int i = tid; i < NM * MAXINV; i += NTHREADS) silist[i] = g_ilist[i];

    // stage ENTIRE A tile: 64 rows x 640 floats = 10240 float4, 20 per thread
    #pragma unroll
    for (int it = 0; it < 20; it++) {
        int idx = tid + it * NTHREADS;
        int r = idx / 160;
        int g = idx - r * 160;
        cp16(sbase + (uint32_t)(r * ASTRIDE + g * 4) * 4,
             enc + (size_t)(row0 + r) * HD + g * 4);
    }
    CP_COMMIT();
    CP_WAIT(0);
    __syncthreads();

    const float* sA = (const float*)smem;

    float acc[2][4][4];
    #pragma unroll
    for (int i = 0; i < 2; i++)
        #pragma unroll
        for (int j = 0; j < 4; j++)
            #pragma unroll
            for (int c = 0; c < 4; c++) acc[i][j][c] = 0.0f;

    uint2 bfrA[4][2], bfrB[4][2];   // [j][ks16], .x = b0 reg, .y = b1 reg

    auto load_b = [&](int kc, uint2 (*bfr)[2]) {
        const uint32_t* bch = g_Bp + (size_t)kc * 4096;
        #pragma unroll
        for (int j = 0; j < 4; j++)
            #pragma unroll
            for (int ks = 0; ks < 2; ks++) {
                int nt = wn * 4 + j;
                bfr[j][ks] = __ldg((const uint2*)(bch + (((nt * 2 + ks) * 32 + lane) << 1)));
            }
    };

    auto mma_chunk = [&](const uint2 (*bfr)[2], int kbase) {
        #pragma unroll
        for (int ks = 0; ks < 2; ks++) {
            uint32_t afr[2][4];
            #pragma unroll
            for (int i = 0; i < 2; i++) {
                const float* ap = sA + (wm * 32 + i * 16 + (lane >> 2)) * ASTRIDE
                                     + kbase + ks * 16 + (lane & 3) * 2;
                float2 v0 = *(const float2*)(ap);                    // row,   k0..k0+1
                float2 v1 = *(const float2*)(ap + 8 * ASTRIDE);      // row+8, k0..k0+1
                float2 v2 = *(const float2*)(ap + 8);                // row,   k0+8..+9
                float2 v3 = *(const float2*)(ap + 8 * ASTRIDE + 8);  // row+8, k0+8..+9
                afr[i][0] = packh2(v0.x, v0.y);
                afr[i][1] = packh2(v1.x, v1.y);
                afr[i][2] = packh2(v2.x, v2.y);
                afr[i][3] = packh2(v3.x, v3.y);
            }
            #pragma unroll
            for (int i = 0; i < 2; i++)
                #pragma unroll
                for (int j = 0; j < 4; j++)
                    mma_f16(acc[i][j], afr[i], bfr[j][ks].x, bfr[j][ks].y);
        }
    };

    // barrier-free mainloop, unrolled x2 to ping-pong B register buffers
    load_b(0, bfrA);
    #pragma unroll 1
    for (int kc = 0; kc < NCHUNK; kc += 2) {
        if (kc + 1 < NCHUNK) load_b(kc + 1, bfrB);
        mma_chunk(bfrA, kc * KC);
        if (kc + 2 < NCHUNK) load_b(kc + 2, bfrA);
        mma_chunk(bfrB, (kc + 1) * KC);
    }
    __syncthreads();   // all warps done reading sA before epilogue aliases it

    // ---- epilogue ----
    const float scale = 0.039528470752104741f;  // 1/sqrt(640)
    float* sPhone = (float*)(smem + SM_PHONE);
    float* sPh    = (float*)(smem + SM_PH);

    #pragma unroll
    for (int i = 0; i < 2; i++) {
        int r = wm * 32 + i * 16 + (lane >> 2);
        #pragma unroll
        for (int j = 0; j < 4; j++) {
            int c = wn * 32 + j * 8 + (lane & 3) * 2;
            float2 v0 = make_float2(acc[i][j][0] * scale, acc[i][j][1] * scale);
            float2 v1 = make_float2(acc[i][j][2] * scale, acc[i][j][3] * scale);
            *(float2*)(sPhone + r * P_PAD + c)       = v0;
            *(float2*)(sPhone + (r + 8) * P_PAD + c) = v1;
        }
    }
    __syncthreads();

    // gather-max via inverse map: 64 rows x 96 phonemes
    for (int idx = tid; idx < TM * NM; idx += NTHREADS) {
        int r = idx / NM;
        int m = idx - r * NM;
        int cnt = sicnt[m];
        const unsigned char* lst = silist + m * MAXINV;
        float mx = -INFINITY;
        for (int c = 0; c < cnt; c++)
            mx = fmaxf(mx, sPhone[r * P_PAD + lst[c]]);
        sPh[r * M_PAD + m] = mx;
    }
    __syncthreads();

    // per-row max + logsumexp: 4 threads per row (first 256 threads)
    if (tid < 256) {
        int r = tid >> 2;
        int q = tid & 3;
        const float* row = sPh + r * M_PAD;
        float mx = -INFINITY;
        #pragma unroll
        for (int m = q * 24; m < q * 24 + 24; m++) mx = fmaxf(mx, row[m]);
        mx = fmaxf(mx, __shfl_xor_sync(0xffffffffu, mx, 1));
        mx = fmaxf(mx, __shfl_xor_sync(0xffffffffu, mx, 2));
        float s = 0.0f;
        #pragma unroll
        for (int m = q * 24; m < q * 24 + 24; m++) s += expf(row[m] - mx);
        s += __shfl_xor_sync(0xffffffffu, s, 1);
        s += __shfl_xor_sync(0xffffffffu, s, 2);
        if (q == 0) { sMaxv[r] = mx; sLsev[r] = logf(s); }
    }
    __syncthreads();

    // coalesced output
    for (int idx = tid; idx < TM * NM; idx += NTHREADS) {
        int r = idx / NM;
        int m = idx - r * NM;
        out[(size_t)(row0 + r) * NM + m] = sPh[r * M_PAD + m] - sMaxv[r] - sLsev[r];
    }
}

extern "C" void kernel_launch(void* const* d_in, const int* in_sizes, int n_in,
                              void* d_out, int out_size) {
    const float* enc     = (const float*)d_in[0];
    const float* f2p     = (const float*)d_in[1];
    const float* mapping = (const float*)d_in[2];
    float*       out     = (float*)d_out;

    cudaFuncSetAttribute(phon_mma_kernel,
                         cudaFuncAttributeMaxDynamicSharedMemorySize, SM_TOTAL);

    prep_kernel<<<NCHUNK + 12, 256>>>(f2p, mapping);
    phon_mma_kernel<<<NROWS / TM, NTHREADS, SM_TOTAL>>>(enc, out);
}

// round 15
// speedup vs baseline: 1.2821x; 1.0790x over previous
#include <cuda_runtime.h>
#include <cuda_fp16.h>
#include <math.h>
#include <stdint.h>

#define NROWS 8192      // B*T
#define HD    640
#define NP    230
#define NM    96
#define TM    64        // rows per CTA
#define KC    32        // k per chunk
#define NCHUNK (HD / KC)  // 20
#define AS_H  648       // A row stride in halves; 1296 B/row -> bank base 4*row, conflict-free
#define P_PAD 258
#define M_PAD 97
#define MAXINV 32
#define NTHREADS 512

// ---- smem byte offsets ----
// A tile fp16: 64 rows x 648 halves = 82944 bytes, converted+stored ONCE.
// epilogue aliases the A region:
#define SM_PHONE 0                        // 64*258*4 = 66048 (< 82944)
#define SM_PH    82944                    // 64*97*4  = 24832 -> 107776
#define SM_TBL   107776                   // icnt 96*4 -> 108160
#define SM_ILIST 108160                   // 96*32    -> 111232
#define SM_MAXV  111232                   // 64*4
#define SM_LSEV  111488                   // 64*4
#define SM_TOTAL 111744

// B packed as fp16x2, one uint4 per (nt, lane):
// [chunk][nt 32][lane 32][ks16 2][reg 2] uint32; 4096 uint32 per chunk.
__device__ uint32_t      g_Bp[NCHUNK * 4096];
__device__ int           g_icnt[NM];
__device__ unsigned char g_ilist[NM * MAXINV];

// ---------------- helpers ----------------
__device__ __forceinline__ uint32_t smem_u32(const void* p) {
    uint32_t a;
    asm("{ .reg .u64 t; cvta.to.shared.u64 t, %1; cvt.u32.u64 %0, t; }" : "=r"(a) : "l"(p));
    return a;
}

// m16n8k16 fp16 MMA, fp32 accum: D += A*B
__device__ __forceinline__ void mma_f16(float* d, const uint32_t* a, uint32_t b0, uint32_t b1) {
    asm volatile(
        "mma.sync.aligned.m16n8k16.row.col.f32.f16.f16.f32 "
        "{%0,%1,%2,%3}, {%4,%5,%6,%7}, {%8,%9}, {%0,%1,%2,%3};"
        : "+f"(d[0]), "+f"(d[1]), "+f"(d[2]), "+f"(d[3])
        : "r"(a[0]), "r"(a[1]), "r"(a[2]), "r"(a[3]), "r"(b0), "r"(b1));
}
// pack two fp32 into fp16x2 (lo -> low half, hi -> high half)
__device__ __forceinline__ uint32_t packh2(float lo, float hi) {
    uint32_t r;
    asm("cvt.rn.f16x2.f32 %0, %1, %2;" : "=r"(r) : "f"(hi), "f"(lo));
    return r;
}

// ---------------- prologue kernel ----------------
// blocks 0..19: pack one 32-row chunk of B into fp16 fragment order (uint4 per nt,lane).
// blocks 20..31: inverse map, ONE phoneme per warp, rounds prefetched.
__global__ void prep_kernel(const float* __restrict__ f2p,
                            const float* __restrict__ mapping) {
    __shared__ float s[32 * 232];
    const int tid = threadIdx.x;
    const int b   = blockIdx.x;
    if (b < NCHUNK) {
        const float* src = f2p + (size_t)b * KC * NP;
        for (int idx = tid; idx < KC * NP; idx += 256) {
            int rr = idx / NP, c = idx - rr * NP;
            s[rr * 232 + c] = src[idx];
        }
        __syncthreads();
        uint32_t* dst = g_Bp + (size_t)b * 4096;
        for (int idx = tid; idx < 4096; idx += 256) {
            // idx = ((nt*32 + lane)*2 + ks)*2 + r2
            int r2   = idx & 1;
            int ks   = (idx >> 1) & 1;
            int lane = (idx >> 2) & 31;
            int nt   = idx >> 7;
            int n = nt * 8 + (lane >> 2);
            int k = ks * 16 + (lane & 3) * 2 + r2 * 8;     // within chunk
            float lo = (n < NP) ? s[k * 232 + n]       : 0.0f;
            float hi = (n < NP) ? s[(k + 1) * 232 + n] : 0.0f;
            dst[idx] = packh2(lo, hi);
        }
    } else {
        int wid  = tid >> 5;
        int lane = tid & 31;
        int m = (b - NCHUNK) * 8 + wid;   // 0..95
        bool hit[8];
        #pragma unroll
        for (int rr = 0; rr < 8; rr++) {
            int p = rr * 32 + lane;
            hit[rr] = (p < NP) && (mapping[m * NP + p] > 0.0f);
        }
        int cnt = 0;
        #pragma unroll
        for (int rr = 0; rr < 8; rr++) {
            unsigned bal = __ballot_sync(0xffffffffu, hit[rr]);
            if (hit[rr]) {
                int pos = cnt + __popc(bal & ((1u << lane) - 1u));
                if (pos < MAXINV) g_ilist[m * MAXINV + pos] = (unsigned char)(rr * 32 + lane);
            }
            cnt += __popc(bal);
        }
        if (lane == 0) g_icnt[m] = (cnt < MAXINV) ? cnt : MAXINV;
    }
}

// ---------------- main kernel ----------------
// 512 threads = 16 warps (2 x 8); warp tile 32 x 32, fp16 m16n8k16.
// A converted to fp16 in smem ONCE; mainloop A-frags are bare LDS.32.
// B fragments one uint4 LDG.128 per (j); prefetched one chunk ahead from L2.
__global__ __launch_bounds__(NTHREADS, 1)
void phon_mma_kernel(const float* __restrict__ enc, float* __restrict__ out) {
    extern __shared__ char smem[];
    const int tid  = threadIdx.x;
    const int wid  = tid >> 5;
    const int lane = tid & 31;
    const int wm   = wid >> 3;   // 0..1  (32-row slice)
    const int wn   = wid & 7;    // 0..7  (32-col slice)
    const int row0 = blockIdx.x * TM;

    int*           sicnt  = (int*)(smem + SM_TBL);
    unsigned char* silist = (unsigned char*)(smem + SM_ILIST);
    float*         sMaxv  = (float*)(smem + SM_MAXV);
    float*         sLsev  = (float*)(smem + SM_LSEV);

    if (tid < NM) sicnt[tid] = g_icnt[tid];
    for (int i = tid; i < NM * MAXINV; i += NTHREADS) silist[i] = g_ilist[i];

    // stage ENTIRE A tile as fp16: LDG.128 -> cvt -> STS.64; 20 float4 per thread
    #pragma unroll
    for (int it = 0; it < 20; it++) {
        int idx = tid + it * NTHREADS;
        int r = idx / 160;           // 160 float4 per row
        int g = idx - r * 160;
        float4 v = *(const float4*)(enc + (size_t)(row0 + r) * HD + g * 4);
        uint2 p = make_uint2(packh2(v.x, v.y), packh2(v.z, v.w));
        *(uint2*)(smem + r * (AS_H * 2) + g * 8) = p;
    }
    __syncthreads();

    const char* sA = smem;   // fp16 A tile, row stride AS_H*2 bytes

    float acc[2][4][4];
    #pragma unroll
    for (int i = 0; i < 2; i++)
        #pragma unroll
        for (int j = 0; j < 4; j++)
            #pragma unroll
            for (int c = 0; c < 4; c++) acc[i][j][c] = 0.0f;

    uint4 bfrA[4], bfrB[4];   // [j]: .x=ks0b0 .y=ks0b1 .z=ks1b0 .w=ks1b1

    auto load_b = [&](int kc, uint4* bfr) {
        const uint32_t* bch = g_Bp + (size_t)kc * 4096;
        #pragma unroll
        for (int j = 0; j < 4; j++) {
            int nt = wn * 4 + j;
            bfr[j] = __ldg((const uint4*)(bch + (((nt * 32 + lane) << 2))));
        }
    };

    auto mma_chunk = [&](const uint4* bfr, int kbase) {
        #pragma unroll
        for (int ks = 0; ks < 2; ks++) {
            uint32_t afr[2][4];
            #pragma unroll
            for (int i = 0; i < 2; i++) {
                const char* ap = sA + (wm * 32 + i * 16 + (lane >> 2)) * (AS_H * 2)
                                    + (kbase + ks * 16 + (lane & 3) * 2) * 2;
                afr[i][0] = *(const uint32_t*)(ap);                      // row,   k0..k0+1
                afr[i][1] = *(const uint32_t*)(ap + 8 * (AS_H * 2));     // row+8, k0..k0+1
                afr[i][2] = *(const uint32_t*)(ap + 16);                 // row,   k0+8..+9
                afr[i][3] = *(const uint32_t*)(ap + 8 * (AS_H * 2) + 16);
            }
            #pragma unroll
            for (int i = 0; i < 2; i++)
                #pragma unroll
                for (int j = 0; j < 4; j++)
                    mma_f16(acc[i][j], afr[i],
                            ks ? bfr[j].z : bfr[j].x,
                            ks ? bfr[j].w : bfr[j].y);
        }
    };

    // barrier-free mainloop, unrolled x2 to ping-pong B register buffers
    load_b(0, bfrA);
    #pragma unroll 1
    for (int kc = 0; kc < NCHUNK; kc += 2) {
        if (kc + 1 < NCHUNK) load_b(kc + 1, bfrB);
        mma_chunk(bfrA, kc * KC);
        if (kc + 2 < NCHUNK) load_b(kc + 2, bfrA);
        mma_chunk(bfrB, (kc + 1) * KC);
    }
    __syncthreads();   // all warps done reading sA before epilogue aliases it

    // ---- epilogue ----
    const float scale = 0.039528470752104741f;  // 1/sqrt(640)
    float* sPhone = (float*)(smem + SM_PHONE);
    float* sPh    = (float*)(smem + SM_PH);

    #pragma unroll
    for (int i = 0; i < 2; i++) {
        int r = wm * 32 + i * 16 + (lane >> 2);
        #pragma unroll
        for (int j = 0; j < 4; j++) {
            int c = wn * 32 + j * 8 + (lane & 3) * 2;
            float2 v0 = make_float2(acc[i][j][0] * scale, acc[i][j][1] * scale);
            float2 v1 = make_float2(acc[i][j][2] * scale, acc[i][j][3] * scale);
            *(float2*)(sPhone + r * P_PAD + c)       = v0;
            *(float2*)(sPhone + (r + 8) * P_PAD + c) = v1;
        }
    }
    __syncthreads();

    // gather-max via inverse map: 64 rows x 96 phonemes
    for (int idx = tid; idx < TM * NM; idx += NTHREADS) {
        int r = idx / NM;
        int m = idx - r * NM;
        int cnt = sicnt[m];
        const unsigned char* lst = silist + m * MAXINV;
        float mx = -INFINITY;
        for (int c = 0; c < cnt; c++)
            mx = fmaxf(mx, sPhone[r * P_PAD + lst[c]]);
        sPh[r * M_PAD + m] = mx;
    }
    __syncthreads();

    // per-row max + logsumexp: 4 threads per row (first 256 threads)
    if (tid < 256) {
        int r = tid >> 2;
        int q = tid & 3;
        const float* row = sPh + r * M_PAD;
        float mx = -INFINITY;
        #pragma unroll
        for (int m = q * 24; m < q * 24 + 24; m++) mx = fmaxf(mx, row[m]);
        mx = fmaxf(mx, __shfl_xor_sync(0xffffffffu, mx, 1));
        mx = fmaxf(mx, __shfl_xor_sync(0xffffffffu, mx, 2));
        float s = 0.0f;
        #pragma unroll
        for (int m = q * 24; m < q * 24 + 24; m++) s += expf(row[m] - mx);
        s += __shfl_xor_sync(0xffffffffu, s, 1);
        s += __shfl_xor_sync(0xffffffffu, s, 2);
        if (q == 0) { sMaxv[r] = mx; sLsev[r] = logf(s); }
    }
    __syncthreads();

    // coalesced output
    for (int idx = tid; idx < TM * NM; idx += NTHREADS) {
        int r = idx / NM;
        int m = idx - r * NM;
        out[(size_t)(row0 + r) * NM + m] = sPh[r * M_PAD + m] - sMaxv[r] - sLsev[r];
    }
}

extern "C" void kernel_launch(void* const* d_in, const int* in_sizes, int n_in,
                              void* d_out, int out_size) {
    const float* enc     = (const float*)d_in[0];
    const float* f2p     = (const float*)d_in[1];
    const float* mapping = (const float*)d_in[2];
    float*       out     = (float*)d_out;

    cudaFuncSetAttribute(phon_mma_kernel,
                         cudaFuncAttributeMaxDynamicSharedMemorySize, SM_TOTAL);

    prep_kernel<<<NCHUNK + 12, 256>>>(f2p, mapping);
    phon_mma_kernel<<<NROWS / TM, NTHREADS, SM_TOTAL>>>(enc, out);
}